// round 7
// baseline (speedup 1.0000x reference)
#include <cuda_runtime.h>
#include <cuda_bf16.h>

// ---------------------------------------------------------------------------
// LatentLayer loss, factorized, single fused kernel (R5):
//   exp(alpha*d_ij) = G[i,k] * H[i,m] * exp(alpha*|e_j|^2),  j = k*1024 + m
//   C[k,m] = sum_i G[i,k]*H[i,m]      (f32x2 FFMA GEMM, K=8192, out 16x1024)
//   lse_j  = alpha*|e_j|^2 + ln(C[k,m])
//   loss   = -mean(lse) + (2*ls - 1) + ln(N)
// Grid: 592 CTAs x 256 thr = 296 K-chunks x 2 column-groups, 4 CTAs/SM
// (one wave at occupancy 4, 32 warps/SM).  Thread owns 2 m-cols x all 16 k
// (32 accumulator registers) -> <=64 regs/thread so 4 CTAs fit.
// Cross-CTA reduction via red.global.add.v2.f32; last CTA does the tail.
// ---------------------------------------------------------------------------

#define N_Z      8192
#define M_EPS    1024
#define N_EMB    16
#define KCHUNKS  296
#define NBLK     (KCHUNKS * 2)     // 592
#define NTHR     256
#define CHUNK    28                // 296*28 = 8288 >= 8192
#define M_TOT    (N_EMB * M_EPS)   // 16384

__device__ __align__(16) float g_C[M_TOT];   // zero-initialized .bss
__device__ unsigned int g_done = 0;

__device__ __forceinline__ float ex2f(float x) {
    float y; asm("ex2.approx.ftz.f32 %0, %1;" : "=f"(y) : "f"(x)); return y;
}
__device__ __forceinline__ float lg2f(float x) {
    float y; asm("lg2.approx.ftz.f32 %0, %1;" : "=f"(y) : "f"(x)); return y;
}
__device__ __forceinline__ unsigned long long pack2(float lo, float hi) {
    unsigned long long r;
    asm("mov.b64 %0, {%1, %2};" : "=l"(r) : "f"(lo), "f"(hi));
    return r;
}
__device__ __forceinline__ void unpack2(unsigned long long v, float& lo, float& hi) {
    asm("mov.b64 {%0, %1}, %2;" : "=f"(lo), "=f"(hi) : "l"(v));
}
__device__ __forceinline__ unsigned long long fma2(unsigned long long a,
                                                   unsigned long long b,
                                                   unsigned long long c) {
    unsigned long long d;
    asm("fma.rn.f32x2 %0, %1, %2, %3;" : "=l"(d) : "l"(a), "l"(b), "l"(c));
    return d;
}

__global__ __launch_bounds__(NTHR, 4)
void fused_kernel(const float* __restrict__ z,
                  const float* __restrict__ emb,
                  const float* __restrict__ lsig,
                  const float* __restrict__ eps,
                  const float* __restrict__ temp,
                  float* __restrict__ out)
{
    __shared__ __align__(16) float2 sGd[CHUNK][N_EMB];  // (g,g) pairs
    __shared__ float2 sZ[CHUNK];       // pre-scaled z
    __shared__ float4 sred[NTHR];      // tail only
    __shared__ int    sIsLast;

    const int   tid = threadIdx.x;
    const int   kchunk = blockIdx.x >> 1;
    const int   colgrp = blockIdx.x & 1;
    const float T   = temp[0];
    const float ls  = lsig[0];
    const float u   = __expf(-2.0f * ls);       // 1/sigma^2
    const float alpha = -0.5f * u;
    const float L2E = 1.4426950408889634f;
    const float LN2 = 0.6931471805599453f;

    const int i0 = kchunk * CHUNK;

    // --- prologue: G[i][k] duplicated, scaled z in smem ---
    for (int t = tid; t < CHUNK * N_EMB; t += NTHR) {
        int il = t >> 4;
        int k  = t & 15;
        int i  = i0 + il;
        float g = 0.0f;
        if (i < N_Z) {
            float zx = z[2 * i], zy = z[2 * i + 1];
            float mx = (1.0f - T) * emb[2 * k];
            float my = (1.0f - T) * emb[2 * k + 1];
            float a  = alpha * (zx * zx + zy * zy) + u * (zx * mx + zy * my);
            g = ex2f(L2E * a);
        }
        sGd[il][k] = make_float2(g, g);
    }
    if (tid < CHUNK) {
        int i = i0 + tid;
        float s  = L2E * u * T;
        float zx = (i < N_Z) ? z[2 * i]     : 0.0f;
        float zy = (i < N_Z) ? z[2 * i + 1] : 0.0f;
        sZ[tid] = make_float2(s * zx, s * zy);
    }
    __syncthreads();

    // --- per-thread pair of m-columns, rotated to spread LTS traffic ---
    const int mbase = colgrp * 512 + 2 * ((tid + kchunk) & 255);

    // eps columns m, m+1: float4 = (x0,y0,x1,y1)
    float4 q = *reinterpret_cast<const float4*>(&eps[2 * mbase]);
    const float ep0x = q.x, ep0y = q.y, ep1x = q.z, ep1y = q.w;

    unsigned long long acc[N_EMB];
#pragma unroll
    for (int k = 0; k < N_EMB; k++) acc[k] = 0ull;

    // --- main loop: H chain + 16 independent fma2 per iter, 8 warps/SMSP ---
#pragma unroll 2
    for (int il = 0; il < CHUNK; il++) {
        float2 zz = sZ[il];
        float b0 = fmaf(zz.x, ep0x, zz.y * ep0y);
        float b1 = fmaf(zz.x, ep1x, zz.y * ep1y);
        unsigned long long h01 = pack2(ex2f(b0), ex2f(b1));

#pragma unroll
        for (int q2 = 0; q2 < N_EMB / 2; q2++) {
            ulonglong2 gg = *reinterpret_cast<const ulonglong2*>(&sGd[il][2 * q2]);
            acc[2 * q2]     = fma2(gg.x, h01, acc[2 * q2]);
            acc[2 * q2 + 1] = fma2(gg.y, h01, acc[2 * q2 + 1]);
        }
    }

    // --- epilogue: vector reductions into global C (2 floats per k) ---
#pragma unroll
    for (int k = 0; k < N_EMB; k++) {
        float c0, c1;
        unpack2(acc[k], c0, c1);
        asm volatile("red.global.add.v2.f32 [%0], {%1, %2};"
                     :: "l"(&g_C[k * M_EPS + mbase]), "f"(c0), "f"(c1)
                     : "memory");
    }
    __threadfence();

    if (tid == 0) {
        unsigned int ticket = atomicAdd(&g_done, 1u);
        sIsLast = (ticket == NBLK - 1);
    }
    __syncthreads();
    if (!sIsLast) return;

    // ===== last block: tail =====
    __threadfence();   // acquire: observe all red results

    // (a) sum of lg2(C) over all 16384 columns, float4 loads, zero-store
    float lgsum = 0.0f;
#pragma unroll
    for (int q2 = 0; q2 < M_TOT / (4 * NTHR); q2++) {   // 16 iters
        int j4 = q2 * NTHR + tid;
        float4 c = reinterpret_cast<float4*>(g_C)[j4];
        reinterpret_cast<float4*>(g_C)[j4] = make_float4(0.f, 0.f, 0.f, 0.f);
        lgsum += lg2f(c.x) + lg2f(c.y) + lg2f(c.z) + lg2f(c.w);
    }

    // (b) closed-form Sum_j |e_j|^2:
    //   = 1024*Sum_k|mk|^2 + 2T*(Sum_k mk)·(Sum_m em) + 16*T^2*Sum_m|em|^2
    float sx = 0.f, sy = 0.f, ss = 0.f;
#pragma unroll
    for (int q2 = 0; q2 < M_EPS / NTHR; q2++) {         // 4 m per thread
        int m = q2 * NTHR + tid;
        float2 e = reinterpret_cast<const float2*>(eps)[m];
        sx += e.x; sy += e.y; ss += e.x * e.x + e.y * e.y;
    }

    sred[tid] = make_float4(lgsum, sx, sy, ss);
    __syncthreads();
#pragma unroll
    for (int s = NTHR / 2; s > 0; s >>= 1) {
        if (tid < s) {
            float4 a = sred[tid], b = sred[tid + s];
            sred[tid] = make_float4(a.x + b.x, a.y + b.y, a.z + b.z, a.w + b.w);
        }
        __syncthreads();
    }
    if (tid == 0) {
        float4 r = sred[0];
        float mkx = 0.f, mky = 0.f, mk2 = 0.f;
        for (int k = 0; k < N_EMB; k++) {
            float mx = (1.0f - T) * emb[2 * k];
            float my = (1.0f - T) * emb[2 * k + 1];
            mkx += mx; mky += my; mk2 += mx * mx + my * my;
        }
        float Se = (float)M_EPS * mk2
                 + 2.0f * T * (mkx * r.y + mky * r.z)
                 + (float)N_EMB * T * T * r.w;
        float sum_lse = alpha * Se + LN2 * r.x;
        g_done = 0;       // reset counter for next replay
        out[0] = -sum_lse / (float)M_TOT + (2.0f * ls - 1.0f) + logf((float)N_Z);
    }
}

// ---------------------------------------------------------------------------
extern "C" void kernel_launch(void* const* d_in, const int* in_sizes, int n_in,
                              void* d_out, int out_size)
{
    const float* z    = (const float*)d_in[0];
    const float* emb  = (const float*)d_in[1];
    const float* lsig = (const float*)d_in[2];
    const float* eps  = (const float*)d_in[3];
    const float* temp = (const float*)d_in[4];
    float* out = (float*)d_out;

    fused_kernel<<<NBLK, NTHR>>>(z, emb, lsig, eps, temp, out);
}

// round 8
// speedup vs baseline: 1.1783x; 1.1783x over previous
#include <cuda_runtime.h>
#include <cuda_bf16.h>

// ---------------------------------------------------------------------------
// LatentLayer loss, factorized, single fused kernel (R7):
//   exp(alpha*d_ij) = G[i,k] * H[i,m] * exp(alpha*|e_j|^2),  j = k*1024 + m
//   C[k,m] = sum_i G[i,k]*H[i,m]
//   lse_j  = alpha*|e_j|^2 + ln(C[k,m])
//   loss   = -mean(lse) + (2*ls - 1) + ln(N)
//
// k-packed f32x2 layout: acc pair = (C[2q,m], C[2q+1,m]); G loads come packed
// straight from smem (4 x LDS.128 per i), H duplicated with one mov.b64.
// Grid: 296 CTAs = 74 K-chunks x 4 column-groups, 256 thr, W=1 col/thread.
// C stored transposed Ct[m][16] so each thread's 16 k are contiguous ->
// epilogue is 4 x red.global.add.v4.f32 (74 contributions per address).
// Last-arriving CTA computes the lse reduction and resets state for replay.
// ---------------------------------------------------------------------------

#define N_Z      8192
#define M_EPS    1024
#define N_EMB    16
#define KCHUNKS  74
#define NBLK     (KCHUNKS * 4)     // 296
#define NTHR     256
#define CHUNK    112               // 74*112 = 8288 >= 8192
#define M_TOT    (N_EMB * M_EPS)   // 16384

__device__ __align__(16) float g_Ct[M_TOT];  // Ct[m][k], zero-initialized .bss
__device__ unsigned int g_done = 0;

__device__ __forceinline__ float ex2f(float x) {
    float y; asm("ex2.approx.ftz.f32 %0, %1;" : "=f"(y) : "f"(x)); return y;
}
__device__ __forceinline__ float lg2f(float x) {
    float y; asm("lg2.approx.ftz.f32 %0, %1;" : "=f"(y) : "f"(x)); return y;
}
__device__ __forceinline__ unsigned long long pack2(float lo, float hi) {
    unsigned long long r;
    asm("mov.b64 %0, {%1, %2};" : "=l"(r) : "f"(lo), "f"(hi));
    return r;
}
__device__ __forceinline__ void unpack2(unsigned long long v, float& lo, float& hi) {
    asm("mov.b64 {%0, %1}, %2;" : "=f"(lo), "=f"(hi) : "l"(v));
}
__device__ __forceinline__ unsigned long long fma2(unsigned long long a,
                                                   unsigned long long b,
                                                   unsigned long long c) {
    unsigned long long d;
    asm("fma.rn.f32x2 %0, %1, %2, %3;" : "=l"(d) : "l"(a), "l"(b), "l"(c));
    return d;
}

__global__ __launch_bounds__(NTHR, 2)
void fused_kernel(const float* __restrict__ z,
                  const float* __restrict__ emb,
                  const float* __restrict__ lsig,
                  const float* __restrict__ eps,
                  const float* __restrict__ temp,
                  float* __restrict__ out)
{
    // sG[il][q] holds (g_{2q}, g_{2q+1}) -- natural packed pairs, no dup
    __shared__ __align__(16) float2 sG[CHUNK][N_EMB / 2];
    __shared__ float2 sZ[CHUNK];       // pre-scaled z: L2E*u*T*z_i
    __shared__ float4 sred[NTHR];      // tail only
    __shared__ int    sIsLast;

    const int   tid    = threadIdx.x;
    const int   kchunk = blockIdx.x >> 2;     // 0..73
    const int   colgrp = blockIdx.x & 3;      // 0..3
    const float T   = temp[0];
    const float ls  = lsig[0];
    const float u   = __expf(-2.0f * ls);     // 1/sigma^2
    const float alpha = -0.5f * u;
    const float L2E = 1.4426950408889634f;
    const float LN2 = 0.6931471805599453f;

    const int i0 = kchunk * CHUNK;

    // --- prologue: packed G[i][k] and scaled z in smem ---
    for (int t = tid; t < CHUNK * N_EMB; t += NTHR) {
        int il = t >> 4;
        int k  = t & 15;
        int i  = i0 + il;
        float g = 0.0f;
        if (i < N_Z) {
            float zx = z[2 * i], zy = z[2 * i + 1];
            float mx = (1.0f - T) * emb[2 * k];
            float my = (1.0f - T) * emb[2 * k + 1];
            float a  = alpha * (zx * zx + zy * zy) + u * (zx * mx + zy * my);
            g = ex2f(L2E * a);
        }
        ((float*)sG)[il * N_EMB + k] = g;     // [il][k] contiguous
    }
    for (int t = tid; t < CHUNK; t += NTHR) {
        int i = i0 + t;
        float s  = L2E * u * T;
        float zx = (i < N_Z) ? z[2 * i]     : 0.0f;
        float zy = (i < N_Z) ? z[2 * i + 1] : 0.0f;
        sZ[t] = make_float2(s * zx, s * zy);
    }
    __syncthreads();

    // --- this thread's single m-column (rotated within group per kchunk) ---
    const int m = colgrp * 256 + ((tid + kchunk * 37) & 255);
    const float2 ep = reinterpret_cast<const float2*>(eps)[m];

    unsigned long long acc[N_EMB / 2];
#pragma unroll
    for (int q = 0; q < N_EMB / 2; q++) acc[q] = 0ull;

    // --- main loop: H chain + 8 packed fma2 + 4 LDS.128 per i ---
#pragma unroll 4
    for (int il = 0; il < CHUNK; il++) {
        float2 zz = sZ[il];
        float b = fmaf(zz.x, ep.x, zz.y * ep.y);
        float h = ex2f(b);
        unsigned long long hh = pack2(h, h);

#pragma unroll
        for (int q = 0; q < N_EMB / 2; q += 2) {
            // one LDS.128 fetches pairs q and q+1
            ulonglong2 gg = *reinterpret_cast<const ulonglong2*>(&sG[il][q]);
            acc[q]     = fma2(gg.x, hh, acc[q]);
            acc[q + 1] = fma2(gg.y, hh, acc[q + 1]);
        }
    }

    // --- epilogue: 4 x red.v4 into transposed C (16 contiguous k) ---
    float c[N_EMB];
#pragma unroll
    for (int q = 0; q < N_EMB / 2; q++) unpack2(acc[q], c[2 * q], c[2 * q + 1]);
#pragma unroll
    for (int q4 = 0; q4 < N_EMB / 4; q4++) {
        asm volatile("red.global.add.v4.f32 [%0], {%1, %2, %3, %4};"
                     :: "l"(&g_Ct[m * N_EMB + 4 * q4]),
                        "f"(c[4 * q4]), "f"(c[4 * q4 + 1]),
                        "f"(c[4 * q4 + 2]), "f"(c[4 * q4 + 3])
                     : "memory");
    }
    __threadfence();

    if (tid == 0) {
        unsigned int ticket = atomicAdd(&g_done, 1u);
        sIsLast = (ticket == NBLK - 1);
    }
    __syncthreads();
    if (!sIsLast) return;

    // ===== last block: tail =====
    __threadfence();   // acquire: observe all red results

    // (a) sum of lg2(Ct) over all 16384 entries, float4 loads, zero-store
    float lgsum = 0.0f;
#pragma unroll
    for (int q2 = 0; q2 < M_TOT / (4 * NTHR); q2++) {   // 16 iters
        int j4 = q2 * NTHR + tid;
        float4 cc = reinterpret_cast<float4*>(g_Ct)[j4];
        reinterpret_cast<float4*>(g_Ct)[j4] = make_float4(0.f, 0.f, 0.f, 0.f);
        lgsum += lg2f(cc.x) + lg2f(cc.y) + lg2f(cc.z) + lg2f(cc.w);
    }

    // (b) closed-form Sum_j |e_j|^2:
    //   = 1024*Sum_k|mk|^2 + 2T*(Sum_k mk)·(Sum_m em) + 16*T^2*Sum_m|em|^2
    float sx = 0.f, sy = 0.f, ss = 0.f;
#pragma unroll
    for (int q2 = 0; q2 < M_EPS / NTHR; q2++) {         // 4 m per thread
        int mm = q2 * NTHR + tid;
        float2 e = reinterpret_cast<const float2*>(eps)[mm];
        sx += e.x; sy += e.y; ss += e.x * e.x + e.y * e.y;
    }

    sred[tid] = make_float4(lgsum, sx, sy, ss);
    __syncthreads();
#pragma unroll
    for (int s = NTHR / 2; s > 0; s >>= 1) {
        if (tid < s) {
            float4 a = sred[tid], b = sred[tid + s];
            sred[tid] = make_float4(a.x + b.x, a.y + b.y, a.z + b.z, a.w + b.w);
        }
        __syncthreads();
    }
    if (tid == 0) {
        float4 r = sred[0];
        float mkx = 0.f, mky = 0.f, mk2 = 0.f;
        for (int k = 0; k < N_EMB; k++) {
            float mx = (1.0f - T) * emb[2 * k];
            float my = (1.0f - T) * emb[2 * k + 1];
            mkx += mx; mky += my; mk2 += mx * mx + my * my;
        }
        float Se = (float)M_EPS * mk2
                 + 2.0f * T * (mkx * r.y + mky * r.z)
                 + (float)N_EMB * T * T * r.w;
        float sum_lse = alpha * Se + LN2 * r.x;
        g_done = 0;       // reset counter for next replay
        out[0] = -sum_lse / (float)M_TOT + (2.0f * ls - 1.0f) + logf((float)N_Z);
    }
}

// ---------------------------------------------------------------------------
extern "C" void kernel_launch(void* const* d_in, const int* in_sizes, int n_in,
                              void* d_out, int out_size)
{
    const float* z    = (const float*)d_in[0];
    const float* emb  = (const float*)d_in[1];
    const float* lsig = (const float*)d_in[2];
    const float* eps  = (const float*)d_in[3];
    const float* temp = (const float*)d_in[4];
    float* out = (float*)d_out;

    fused_kernel<<<NBLK, NTHR>>>(z, emb, lsig, eps, temp, out);
}